// round 1
// baseline (speedup 1.0000x reference)
#include <cuda_runtime.h>
#include <cstdint>

// RadialAEVComputer: GR[b,i,s,p] = sum_j exp(-eta*(d_bij - shf_p)^2) * fc(d_bij) * [spec_bj == s+1]
// B=64, N=256, S=4, P=16 (eta=16, shf = 0.9 + 0.26875*p), RC=5.2
//
// One warp per (b,i) row; lane-per-j; 64 register accumulators per lane;
// branchless species scatter via 4 select weights; shuffle-tree allreduce.

#define WARPS_PER_BLOCK 8

__global__ __launch_bounds__(256, 2)
void radial_aev_kernel(const float* __restrict__ dmat,
                       const int*   __restrict__ spec,
                       float*       __restrict__ out,
                       int N)
{
    __shared__ int sspec[256];

    const int lane = threadIdx.x & 31;
    const int wid  = threadIdx.x >> 5;
    const int rowBase = blockIdx.x * WARPS_PER_BLOCK;   // N=256 divisible by 8 -> one b per block
    const int b = rowBase / N;

    // stage species row for this batch element
    if (threadIdx.x < N)
        sspec[threadIdx.x] = spec[b * N + threadIdx.x];
    __syncthreads();

    const int row = rowBase + wid;            // b*N + i
    const float* __restrict__ drow = dmat + (size_t)row * N;

    float acc[64];
#pragma unroll
    for (int m = 0; m < 64; ++m) acc[m] = 0.0f;

    const float RC      = 5.2f;
    const float PI_RC   = 0.60415244f;           // pi / 5.2
    const float NEGETA_LOG2E = -23.083120654f;   // -16 * log2(e)

    for (int j0 = 0; j0 < N; j0 += 32) {
        const int j = j0 + lane;
        const float dj = drow[j];
        const int   sj = sspec[j];

        const bool incut = (dj < RC) && (dj != 0.0f);
        float fc = fmaf(0.5f, __cosf(dj * PI_RC), 0.5f);
        const float fcm = incut ? fc : 0.0f;

        const float w0 = (sj == 1) ? fcm : 0.0f;
        const float w1 = (sj == 2) ? fcm : 0.0f;
        const float w2 = (sj == 3) ? fcm : 0.0f;
        const float w3 = (sj == 4) ? fcm : 0.0f;

#pragma unroll
        for (int p = 0; p < 16; ++p) {
            const float shf = 0.9f + 0.26875f * (float)p;   // compile-time constant
            const float x  = dj - shf;
            const float a  = (x * x) * NEGETA_LOG2E;        // -eta*x^2 in log2 domain
            float t;
            asm("ex2.approx.ftz.f32 %0, %1;" : "=f"(t) : "f"(a));
            acc[p]      = fmaf(t, w0, acc[p]);
            acc[16 + p] = fmaf(t, w1, acc[16 + p]);
            acc[32 + p] = fmaf(t, w2, acc[32 + p]);
            acc[48 + p] = fmaf(t, w3, acc[48 + p]);
        }
    }

    // Multi-value warp allreduce: after 5 halving steps, lane L owns flat
    // indices 2L and 2L+1 (flat = s*16 + p).
    int n = 64;
#pragma unroll
    for (int step = 16; step >= 1; step >>= 1) {
        n >>= 1;
        const bool up = (lane & step) != 0;
#pragma unroll
        for (int m = 0; m < n; ++m) {
            const float keep = up ? acc[m + n] : acc[m];
            const float send = up ? acc[m] : acc[m + n];
            acc[m] = keep + __shfl_xor_sync(0xffffffffu, send, step);
        }
    }

    // coalesced float2 store: out[row*64 + 2*lane + {0,1}]
    float2 v = make_float2(acc[0], acc[1]);
    reinterpret_cast<float2*>(out)[(size_t)row * 32 + lane] = v;
}

extern "C" void kernel_launch(void* const* d_in, const int* in_sizes, int n_in,
                              void* d_out, int out_size)
{
    const float* dmat;
    const int*   spec;
    int sz_d, sz_s;
    if (in_sizes[0] > in_sizes[1]) {
        dmat = (const float*)d_in[0]; spec = (const int*)d_in[1];
        sz_d = in_sizes[0]; sz_s = in_sizes[1];
    } else {
        dmat = (const float*)d_in[1]; spec = (const int*)d_in[0];
        sz_d = in_sizes[1]; sz_s = in_sizes[0];
    }
    const int N    = sz_d / sz_s;   // 256
    const int rows = sz_s;          // B*N = 16384

    dim3 grid(rows / WARPS_PER_BLOCK);
    dim3 block(32 * WARPS_PER_BLOCK);
    radial_aev_kernel<<<grid, block>>>(dmat, spec, (float*)d_out, N);
}

// round 2
// speedup vs baseline: 1.5863x; 1.5863x over previous
#include <cuda_runtime.h>
#include <cstdint>

// RadialAEVComputer: GR[b,i,s,p] = sum_j exp(-16*(d_bij - shf_p)^2) * fc(d_bij) * [spec_bj == s+1]
// B=64, N=256, S=4, P=16, shf_p = 0.9 + 0.26875*p, RC=5.2
//
// R2 design: per-(b,i) warp.
//   Pass 1: stream row, cutoff-compact (d, fc|spec) into per-warp smem (~22% survive).
//   Pass 2: compacted pairs; Gaussian arg via expanded imm-FMA form; packed f32x2
//           accumulate (4 species scatter -> 4 FFMA2 per p-pair).
//   Packed butterfly allreduce; lane L ends owning flat outputs (2L, 2L+1).

#define WARPS_PER_BLOCK 4

__device__ __forceinline__ unsigned long long pack2(float lo, float hi) {
    unsigned long long r;
    asm("mov.b64 %0, {%1, %2};" : "=l"(r) : "f"(lo), "f"(hi));
    return r;
}
__device__ __forceinline__ void fma2_acc(unsigned long long& d,
                                         unsigned long long a,
                                         unsigned long long b) {
    asm("fma.rn.f32x2 %0, %1, %2, %0;" : "+l"(d) : "l"(a), "l"(b));
}
__device__ __forceinline__ unsigned long long add2(unsigned long long a,
                                                   unsigned long long b) {
    unsigned long long r;
    asm("add.rn.f32x2 %0, %1, %2;" : "=l"(r) : "l"(a), "l"(b));
    return r;
}
__device__ __forceinline__ float ex2f(float a) {
    float t;
    asm("ex2.approx.ftz.f32 %0, %1;" : "=f"(t) : "f"(a));
    return t;
}

__global__ __launch_bounds__(32 * WARPS_PER_BLOCK, 5)
void radial_aev_kernel(const float* __restrict__ dmat,
                       const int*   __restrict__ spec,
                       float*       __restrict__ out,
                       int N)
{
    __shared__ int   sspec[256];
    __shared__ float sd[WARPS_PER_BLOCK][256];
    __shared__ float sf[WARPS_PER_BLOCK][256];

    const int lane = threadIdx.x & 31;
    const int wid  = threadIdx.x >> 5;
    const int rowBase = blockIdx.x * WARPS_PER_BLOCK;   // 256 % 4 == 0 -> one b per block
    const int b = rowBase / N;

    // stage species row for this batch element
    for (int t = threadIdx.x; t < N; t += 32 * WARPS_PER_BLOCK)
        sspec[t] = spec[b * N + t];
    __syncthreads();

    const int row = rowBase + wid;            // b*N + i
    const float* __restrict__ drow = dmat + (size_t)row * N;

    const float RC    = 5.2f;
    const float PI_RC = 0.60415244f;            // pi / 5.2
    const float NL    = -23.083120654f;         // -16 * log2(e)
    const float P2L   = 46.166241309f;          // +32 * log2(e)  (= -2*NL)

    // ---- Pass 1: cutoff compaction into per-warp smem ----
    unsigned cnt = 0;
    for (int j0 = 0; j0 < N; j0 += 32) {
        const int j = j0 + lane;
        const float dj = drow[j];
        const int   sj = sspec[j];
        const bool incut = (dj < RC) && (dj != 0.0f);
        const unsigned m = __ballot_sync(0xffffffffu, incut);
        if (incut) {
            float fc = fmaf(0.5f, __cosf(dj * PI_RC), 0.5f);
            // stash (species-1) in the 2 LSBs of fc's mantissa (<=3 ulp error)
            float fcp = __int_as_float((__float_as_int(fc) & ~3) | (sj - 1));
            int pos = cnt + __popc(m & ((1u << lane) - 1u));
            sd[wid][pos] = dj;
            sf[wid][pos] = fcp;
        }
        cnt += __popc(m);
    }
    const int Mr = (cnt + 31) & ~31;            // <= 256
    if ((int)(cnt + lane) < Mr) {               // zero-pad partial chunk
        sd[wid][cnt + lane] = 0.0f;
        sf[wid][cnt + lane] = 0.0f;             // code 0, weight 0 -> no contribution
    }
    __syncwarp();

    // ---- Pass 2: compacted Gaussian accumulation, packed f32x2 ----
    unsigned long long acc2[32];                // acc2[s*8+pp] = (flat 2m, 2m+1), m = s*8+pp
#pragma unroll
    for (int m = 0; m < 32; ++m) acc2[m] = 0ull;

    for (int k = lane; k < Mr; k += 32) {
        const float dj = sd[wid][k];
        const int   fb = __float_as_int(sf[wid][k]);
        const int   code = fb & 3;
        const float fcv  = __int_as_float(fb);

        const float w0 = (code == 0) ? fcv : 0.0f;
        const float w1 = (code == 1) ? fcv : 0.0f;
        const float w2 = (code == 2) ? fcv : 0.0f;
        const float w3 = (code == 3) ? fcv : 0.0f;
        const unsigned long long ww0 = pack2(w0, w0);
        const unsigned long long ww1 = pack2(w1, w1);
        const unsigned long long ww2 = pack2(w2, w2);
        const unsigned long long ww3 = pack2(w3, w3);

        // a_p = NL*(d - s_p)^2 = A + Bv*s_p + C_p,  A = NL*d^2, Bv = P2L*d, C_p = NL*s_p^2
        const float A  = (dj * dj) * NL;
        const float Bv = P2L * dj;

#pragma unroll
        for (int pp = 0; pp < 8; ++pp) {
            const float s0 = 0.9f + 0.26875f * (float)(2 * pp);
            const float s1 = 0.9f + 0.26875f * (float)(2 * pp + 1);
            const float c0 = NL * s0 * s0;      // compile-time
            const float c1 = NL * s1 * s1;
            float a0 = fmaf(Bv, s0, A) + c0;
            float a1 = fmaf(Bv, s1, A) + c1;
            const float t0 = ex2f(a0);
            const float t1 = ex2f(a1);
            const unsigned long long tt = pack2(t0, t1);
            fma2_acc(acc2[pp],      tt, ww0);
            fma2_acc(acc2[8 + pp],  tt, ww1);
            fma2_acc(acc2[16 + pp], tt, ww2);
            fma2_acc(acc2[24 + pp], tt, ww3);
        }
    }

    // ---- Packed multi-value butterfly allreduce ----
    // 32 packed values; after 5 halving steps lane L owns packed[L] = flats (2L, 2L+1).
    int n = 32;
#pragma unroll
    for (int step = 16; step >= 1; step >>= 1) {
        n >>= 1;
        const bool up = (lane & step) != 0;
#pragma unroll
        for (int m = 0; m < n; ++m) {
            const unsigned long long keep = up ? acc2[m + n] : acc2[m];
            const unsigned long long send = up ? acc2[m] : acc2[m + n];
            const unsigned long long rec  = __shfl_xor_sync(0xffffffffu, send, step);
            acc2[m] = add2(keep, rec);
        }
    }

    float2 v;
    v.x = __int_as_float((int)(acc2[0] & 0xffffffffull));
    v.y = __int_as_float((int)(acc2[0] >> 32));
    reinterpret_cast<float2*>(out)[(size_t)row * 32 + lane] = v;
}

extern "C" void kernel_launch(void* const* d_in, const int* in_sizes, int n_in,
                              void* d_out, int out_size)
{
    const float* dmat;
    const int*   spec;
    int sz_d, sz_s;
    if (in_sizes[0] > in_sizes[1]) {
        dmat = (const float*)d_in[0]; spec = (const int*)d_in[1];
        sz_d = in_sizes[0]; sz_s = in_sizes[1];
    } else {
        dmat = (const float*)d_in[1]; spec = (const int*)d_in[0];
        sz_d = in_sizes[1]; sz_s = in_sizes[0];
    }
    const int N    = sz_d / sz_s;   // 256
    const int rows = sz_s;          // B*N = 16384

    dim3 grid(rows / WARPS_PER_BLOCK);
    dim3 block(32 * WARPS_PER_BLOCK);
    radial_aev_kernel<<<grid, block>>>(dmat, spec, (float*)d_out, N);
}

// round 3
// speedup vs baseline: 1.7580x; 1.1083x over previous
#include <cuda_runtime.h>
#include <cstdint>

// RadialAEVComputer: GR[b,i,s,p] = sum_j exp(-16*(d_bij - shf_p)^2) * fc(d_bij) * [spec_bj == s+1]
// B=64, N=256, S=4, P=16, shf_p = 0.9 + 0.26875*p, RC=5.2
//
// R3: per-(b,i) warp.
//   Pass 1: cutoff-compact packed (d | species-in-2-LSBs) into per-warp smem list.
//   Pass 2: lane-pair split -- lane handles p-half (lane&1), processes its own
//           neighbor + partner's (2 shuffles); 16 packed f32x2 accumulators.
//   Reduction: smem transpose (16 STS.64 + 16 LDS.64 + 16 add2), no butterfly.

#define WPB 4
#define FULL 0xffffffffu

__device__ __forceinline__ unsigned long long pack2(float lo, float hi) {
    unsigned long long r;
    asm("mov.b64 %0, {%1, %2};" : "=l"(r) : "f"(lo), "f"(hi));
    return r;
}
__device__ __forceinline__ void fma2_acc(unsigned long long& d,
                                         unsigned long long a,
                                         unsigned long long b) {
    asm("fma.rn.f32x2 %0, %1, %2, %0;" : "+l"(d) : "l"(a), "l"(b));
}
__device__ __forceinline__ unsigned long long add2(unsigned long long a,
                                                   unsigned long long b) {
    unsigned long long r;
    asm("add.rn.f32x2 %0, %1, %2;" : "=l"(r) : "l"(a), "l"(b));
    return r;
}
__device__ __forceinline__ float ex2f(float a) {
    float t;
    asm("ex2.approx.ftz.f32 %0, %1;" : "=f"(t) : "f"(a));
    return t;
}

__global__ __launch_bounds__(32 * WPB, 6)
void radial_aev_kernel(const float* __restrict__ dmat,
                       const int*   __restrict__ spec,
                       float*       __restrict__ out,
                       int N)
{
    __shared__ int   sspec[256];
    __shared__ float slist[WPB][256];
    __shared__ unsigned long long trb[WPB][32][17];   // padded rows vs bank conflicts

    const int lane = threadIdx.x & 31;
    const int wid  = threadIdx.x >> 5;
    const int rowBase = blockIdx.x * WPB;             // one batch elem per block (256 % 4 == 0)
    const int b = rowBase / N;

    for (int t = threadIdx.x; t < N; t += 32 * WPB)
        sspec[t] = spec[b * N + t];
    __syncthreads();

    const int row = rowBase + wid;                    // b*N + i
    const float* __restrict__ drow = dmat + (size_t)row * N;

    const float RC    = 5.2f;
    const float PI_RC = 0.60415244f;                  // pi / 5.2
    const float NL    = -23.083120654f;               // -16 * log2(e)
    const float P2L   = 46.166241309f;                // +32 * log2(e)

    // ---- Pass 1: cutoff compaction; store d with species code in 2 LSBs ----
    unsigned cnt = 0;
    for (int j0 = 0; j0 < N; j0 += 32) {
        const int j = j0 + lane;
        const float dj = drow[j];
        const int   sj = sspec[j];
        const bool incut = (dj < RC) && (dj != 0.0f);
        const unsigned m = __ballot_sync(FULL, incut);
        if (incut) {
            unsigned bits = (__float_as_uint(dj) & ~3u) | (unsigned)(sj - 1);
            slist[wid][cnt + __popc(m & ((1u << lane) - 1u))] = __uint_as_float(bits);
        }
        cnt += __popc(m);
    }
    const int Mr = (int)((cnt + 31u) & ~31u);
    if ((int)cnt + lane < Mr)
        slist[wid][cnt + lane] = 1.0e9f;              // sentinel: d >= RC -> weight 0, ex2 -> 0
    __syncwarp();

    // ---- per-lane p-half shift constants: p = 8*(lane&1) + q, q = 0..7 ----
    const int   h     = lane & 1;
    const float sbase = 0.9f + 2.15f * (float)h;      // 0.26875 * 8 = 2.15
    float sp[8], cp[8];
#pragma unroll
    for (int q = 0; q < 8; ++q) {
        sp[q] = sbase + 0.26875f * (float)q;
        cp[q] = NL * sp[q] * sp[q];
    }

    // ---- Pass 2: compacted accumulation, lane-pair split ----
    unsigned long long acc2[16];                      // acc2[s*4+u] = p (8h+2u, 8h+2u+1)
#pragma unroll
    for (int m = 0; m < 16; ++m) acc2[m] = 0ull;

    for (int base = 0; base < Mr; base += 32) {
        const unsigned bits0 = __float_as_uint(slist[wid][base + lane]);
        const float    d0    = __uint_as_float(bits0);
        const float    pk1   = __shfl_xor_sync(FULL, d0, 1);
        const unsigned bits1 = __float_as_uint(pk1);
        const float    d1    = pk1;
        const int c0 = bits0 & 3;
        const int c1 = bits1 & 3;

        const float fc0 = fmaf(0.5f, __cosf(d0 * PI_RC), 0.5f);
        const float ws0 = (d0 < RC) ? fc0 : 0.0f;
        const float ws1 = __shfl_xor_sync(FULL, ws0, 1);

        const float A0 = d0 * d0 * NL, B0 = P2L * d0;
        const float A1 = d1 * d1 * NL, B1 = P2L * d1;

        unsigned long long tt0[4], tt1[4];
#pragma unroll
        for (int u = 0; u < 4; ++u) {
            const float a0l = fmaf(B0, sp[2 * u],     A0) + cp[2 * u];
            const float a0h = fmaf(B0, sp[2 * u + 1], A0) + cp[2 * u + 1];
            tt0[u] = pack2(ex2f(a0l), ex2f(a0h));
            const float a1l = fmaf(B1, sp[2 * u],     A1) + cp[2 * u];
            const float a1h = fmaf(B1, sp[2 * u + 1], A1) + cp[2 * u + 1];
            tt1[u] = pack2(ex2f(a1l), ex2f(a1h));
        }
#pragma unroll
        for (int s = 0; s < 4; ++s) {
            const float w0 = (c0 == s) ? ws0 : 0.0f;
            const float w1 = (c1 == s) ? ws1 : 0.0f;
            const unsigned long long ww0 = pack2(w0, w0);
            const unsigned long long ww1 = pack2(w1, w1);
#pragma unroll
            for (int u = 0; u < 4; ++u) {
                fma2_acc(acc2[s * 4 + u], tt0[u], ww0);
                fma2_acc(acc2[s * 4 + u], tt1[u], ww1);
            }
        }
    }

    // ---- Reduction via smem transpose ----
    // Lane k's acc2[s*4+u] holds p-half (k&1). Output flat f = s*16+p; lane L
    // finalizes f = 2L, 2L+1: s=L/8, p0=2L%16, hout=p0>>3, u=(p0&7)>>1.
#pragma unroll
    for (int m = 0; m < 16; ++m) trb[wid][lane][m] = acc2[m];
    __syncwarp();

    const int s_o  = lane >> 3;
    const int p0   = (2 * lane) & 15;
    const int hout = p0 >> 3;
    const int slot = s_o * 4 + ((p0 & 7) >> 1);
    unsigned long long sum = 0ull;
#pragma unroll
    for (int t = 0; t < 16; ++t) {
        const int k = (((t + lane) & 15) << 1) | hout;   // staggered, parity hout
        sum = add2(sum, trb[wid][k][slot]);
    }

    float2 v;
    v.x = __int_as_float((int)(sum & 0xffffffffull));
    v.y = __int_as_float((int)(sum >> 32));
    reinterpret_cast<float2*>(out)[(size_t)row * 32 + lane] = v;
}

extern "C" void kernel_launch(void* const* d_in, const int* in_sizes, int n_in,
                              void* d_out, int out_size)
{
    const float* dmat;
    const int*   spec;
    int sz_d, sz_s;
    if (in_sizes[0] > in_sizes[1]) {
        dmat = (const float*)d_in[0]; spec = (const int*)d_in[1];
        sz_d = in_sizes[0]; sz_s = in_sizes[1];
    } else {
        dmat = (const float*)d_in[1]; spec = (const int*)d_in[0];
        sz_d = in_sizes[1]; sz_s = in_sizes[0];
    }
    const int N    = sz_d / sz_s;   // 256
    const int rows = sz_s;          // B*N = 16384

    dim3 grid(rows / WPB);
    dim3 block(32 * WPB);
    radial_aev_kernel<<<grid, block>>>(dmat, spec, (float*)d_out, N);
}

// round 4
// speedup vs baseline: 2.2441x; 1.2765x over previous
#include <cuda_runtime.h>
#include <cstdint>

// RadialAEVComputer: GR[b,i,s,p] = sum_j exp(-16*(d_bij - shf_p)^2) * fc(d_bij) * [spec_bj == s+1]
// B=64, N=256, S=4, P=16, shf_p = 0.9 + 0.26875*p, RC=5.2
//
// R4: per-(b,i) warp; 50%-occupancy build.
//   Pass 1: float4/int4 streaming cutoff-compaction (2 iters), species read direct
//           from gmem (L1-hot), packed (d | species) list in smem.
//   Pass 2: lane-pair p-split; Gaussian arg x*(x*NL) with immediate-constant
//           shifts (no sp/cp register tables); neighbor-serial weight blocks.
//   Reduction: smem transpose (16 STS.64 + 16 LDS.64 + 16 add2).

#define WPB 4
#define FULL 0xffffffffu

__device__ __forceinline__ unsigned long long pack2(float lo, float hi) {
    unsigned long long r;
    asm("mov.b64 %0, {%1, %2};" : "=l"(r) : "f"(lo), "f"(hi));
    return r;
}
__device__ __forceinline__ void fma2_acc(unsigned long long& d,
                                         unsigned long long a,
                                         unsigned long long b) {
    asm("fma.rn.f32x2 %0, %1, %2, %0;" : "+l"(d) : "l"(a), "l"(b));
}
__device__ __forceinline__ unsigned long long add2(unsigned long long a,
                                                   unsigned long long b) {
    unsigned long long r;
    asm("add.rn.f32x2 %0, %1, %2;" : "=l"(r) : "l"(a), "l"(b));
    return r;
}
__device__ __forceinline__ float ex2f(float a) {
    float t;
    asm("ex2.approx.ftz.f32 %0, %1;" : "=f"(t) : "f"(a));
    return t;
}

__global__ __launch_bounds__(32 * WPB, 8)
void radial_aev_kernel(const float* __restrict__ dmat,
                       const int*   __restrict__ spec,
                       float*       __restrict__ out,
                       int N)
{
    __shared__ float slist[WPB][256];
    __shared__ unsigned long long trb[WPB][32][17];   // padded vs bank conflicts

    const int lane = threadIdx.x & 31;
    const int wid  = threadIdx.x >> 5;
    const int row  = blockIdx.x * WPB + wid;          // b*N + i
    const int b    = row >> 8;                        // N == 256

    const float* __restrict__ drow = dmat + (size_t)row * N;
    const int*   __restrict__ srow = spec + b * N;

    const float RC    = 5.2f;
    const float PI_RC = 0.60415244f;                  // pi / 5.2
    const float NL    = -23.083120654f;               // -16 * log2(e)
    const unsigned lmlt = (1u << lane) - 1u;

    // ---- Pass 1: float4 cutoff compaction; d with species code in 2 LSBs ----
    unsigned cnt = 0;
    const float4* __restrict__ drow4 = (const float4*)drow;
    const int4*   __restrict__ srow4 = (const int4*)srow;
#pragma unroll
    for (int it = 0; it < 2; ++it) {
        const float4 dv = drow4[it * 32 + lane];
        const int4   sv = srow4[it * 32 + lane];
#pragma unroll
        for (int c = 0; c < 4; ++c) {
            const float d = (c == 0) ? dv.x : (c == 1) ? dv.y : (c == 2) ? dv.z : dv.w;
            const int   s = (c == 0) ? sv.x : (c == 1) ? sv.y : (c == 2) ? sv.z : sv.w;
            const bool in = (d < RC) && (d != 0.0f);
            const unsigned m = __ballot_sync(FULL, in);
            if (in) {
                const unsigned bits = (__float_as_uint(d) & ~3u) | (unsigned)(s - 1);
                slist[wid][cnt + __popc(m & lmlt)] = __uint_as_float(bits);
            }
            cnt += __popc(m);
        }
    }
    const int Mr = (int)((cnt + 31u) & ~31u);
    if ((int)cnt + lane < Mr)
        slist[wid][cnt + lane] = 1.0e9f;              // sentinel: weight 0, ex2 -> 0
    __syncwarp();

    // ---- Pass 2: compacted accumulation, lane-pair p-split ----
    const int   h     = lane & 1;                     // p-half: p = 8h + 2u + {0,1}
    const float sbase = fmaf(2.15f, (float)h, 0.9f);  // 0.26875 * 8 = 2.15

    unsigned long long acc2[16];                      // acc2[s*4+u]
#pragma unroll
    for (int m = 0; m < 16; ++m) acc2[m] = 0ull;

    for (int base = 0; base < Mr; base += 32) {
        const unsigned bits0 = __float_as_uint(slist[wid][base + lane]);
        const float    d0    = __uint_as_float(bits0);
        const float    d1    = __shfl_xor_sync(FULL, d0, 1);
        const unsigned bits1 = __float_as_uint(d1);
        const int c0 = bits0 & 3;
        const int c1 = bits1 & 3;

        const float fc0 = fmaf(0.5f, __cosf(d0 * PI_RC), 0.5f);
        const float ws0 = (d0 < RC) ? fc0 : 0.0f;
        const float ws1 = __shfl_xor_sync(FULL, ws0, 1);

        const float dh0 = d0 - sbase;
        const float dh1 = d1 - sbase;

        // neighbor 0
        {
            const float w0 = (c0 == 0) ? ws0 : 0.0f;
            const float w1 = (c0 == 1) ? ws0 : 0.0f;
            const float w2 = (c0 == 2) ? ws0 : 0.0f;
            const float w3 = (c0 == 3) ? ws0 : 0.0f;
            const unsigned long long ww0 = pack2(w0, w0);
            const unsigned long long ww1 = pack2(w1, w1);
            const unsigned long long ww2 = pack2(w2, w2);
            const unsigned long long ww3 = pack2(w3, w3);
#pragma unroll
            for (int u = 0; u < 4; ++u) {
                const float xa = dh0 - 0.26875f * (float)(2 * u);
                const float xb = dh0 - 0.26875f * (float)(2 * u + 1);
                const float aa = xa * (xa * NL);
                const float ab = xb * (xb * NL);
                const unsigned long long tt = pack2(ex2f(aa), ex2f(ab));
                fma2_acc(acc2[u],      tt, ww0);
                fma2_acc(acc2[4 + u],  tt, ww1);
                fma2_acc(acc2[8 + u],  tt, ww2);
                fma2_acc(acc2[12 + u], tt, ww3);
            }
        }
        // neighbor 1
        {
            const float w0 = (c1 == 0) ? ws1 : 0.0f;
            const float w1 = (c1 == 1) ? ws1 : 0.0f;
            const float w2 = (c1 == 2) ? ws1 : 0.0f;
            const float w3 = (c1 == 3) ? ws1 : 0.0f;
            const unsigned long long ww0 = pack2(w0, w0);
            const unsigned long long ww1 = pack2(w1, w1);
            const unsigned long long ww2 = pack2(w2, w2);
            const unsigned long long ww3 = pack2(w3, w3);
#pragma unroll
            for (int u = 0; u < 4; ++u) {
                const float xa = dh1 - 0.26875f * (float)(2 * u);
                const float xb = dh1 - 0.26875f * (float)(2 * u + 1);
                const float aa = xa * (xa * NL);
                const float ab = xb * (xb * NL);
                const unsigned long long tt = pack2(ex2f(aa), ex2f(ab));
                fma2_acc(acc2[u],      tt, ww0);
                fma2_acc(acc2[4 + u],  tt, ww1);
                fma2_acc(acc2[8 + u],  tt, ww2);
                fma2_acc(acc2[12 + u], tt, ww3);
            }
        }
    }

    // ---- Reduction via smem transpose ----
    // Lane k holds p-half (k&1). Output flat f = s*16+p; lane L finalizes
    // f = 2L, 2L+1: s = L>>3, p0 = (2L)&15, hout = p0>>3, u = (p0&7)>>1.
#pragma unroll
    for (int m = 0; m < 16; ++m) trb[wid][lane][m] = acc2[m];
    __syncwarp();

    const int s_o  = lane >> 3;
    const int p0   = (2 * lane) & 15;
    const int hout = p0 >> 3;
    const int slot = s_o * 4 + ((p0 & 7) >> 1);
    unsigned long long sum = 0ull;
#pragma unroll
    for (int t = 0; t < 16; ++t) {
        const int k = (((t + lane) & 15) << 1) | hout;   // staggered, parity hout
        sum = add2(sum, trb[wid][k][slot]);
    }

    float2 v;
    v.x = __int_as_float((int)(sum & 0xffffffffull));
    v.y = __int_as_float((int)(sum >> 32));
    reinterpret_cast<float2*>(out)[(size_t)row * 32 + lane] = v;
}

extern "C" void kernel_launch(void* const* d_in, const int* in_sizes, int n_in,
                              void* d_out, int out_size)
{
    const float* dmat;
    const int*   spec;
    int sz_d, sz_s;
    if (in_sizes[0] > in_sizes[1]) {
        dmat = (const float*)d_in[0]; spec = (const int*)d_in[1];
        sz_d = in_sizes[0]; sz_s = in_sizes[1];
    } else {
        dmat = (const float*)d_in[1]; spec = (const int*)d_in[0];
        sz_d = in_sizes[1]; sz_s = in_sizes[0];
    }
    const int N    = sz_d / sz_s;   // 256
    const int rows = sz_s;          // B*N = 16384

    dim3 grid(rows / WPB);
    dim3 block(32 * WPB);
    radial_aev_kernel<<<grid, block>>>(dmat, spec, (float*)d_out, N);
}